// round 11
// baseline (speedup 1.0000x reference)
#include <cuda_runtime.h>
#include <cuda_bf16.h>

// Problem constants
#define S_   8192
#define LC_  16
#define D_   256
#define CV_  128
#define DC_  64
#define HC_  128
#define H_   256
#define T_   17
// derived
#define G4C  (4*HC_)        // 512 char gates
#define G4W  (4*H_)         // 1024 word gates
#define KW   (HC_ + H_)     // 384 recurrent-x length for word LSTM

typedef unsigned long long ull;

// ---------------- device scratch (no allocation allowed) ----------------
__device__ __align__(16) float g_xg_tab[CV_ * G4C];        // 256 KB: per-char input gates
__device__ __align__(16) float g_wg[S_ * G4W];             // 32 MB : word-emb gate contributions (+b_w)
__device__ __align__(16) float g_WcatT[(KW/4) * G4W * 4];  // 1.5 MB: [k4][1024][4] k-major (hc|hw part)
__device__ __align__(16) float g_WweT[(D_/4) * G4W * 4];   // 1 MB  : [k4][1024][4] k-major (we part)

// ---------------- helpers ----------------
__device__ __forceinline__ void fma2(ull &acc, ull a, ull b) {
    asm("fma.rn.f32x2 %0, %1, %2, %0;" : "+l"(acc) : "l"(a), "l"(b));
}
__device__ __forceinline__ float redu(ull a) {
    return __uint_as_float((unsigned)(a & 0xffffffffull)) +
           __uint_as_float((unsigned)(a >> 32));
}
__device__ __forceinline__ float sigf(float x) {
    return __fdividef(1.0f, 1.0f + __expf(-x));
}
__device__ __forceinline__ float tanh_(float x) {
    float e = __expf(-2.0f * fabsf(x));
    float r = __fdividef(1.0f - e, 1.0f + e);
    return copysignf(r, x);
}

// ---------------- K0: per-char gate table ----------------
__global__ void xg_kernel(const float* __restrict__ Wih_c,
                          const float* __restrict__ char_emb,
                          const float* __restrict__ b_c) {
    __shared__ float ce[DC_];
    const int c = blockIdx.x, t = threadIdx.x;   // 128 blocks x 512 threads
    if (t < DC_) ce[t] = char_emb[c * DC_ + t];
    __syncthreads();
    float acc = b_c[t];
#pragma unroll
    for (int d = 0; d < DC_; ++d) acc += Wih_c[t * DC_ + d] * ce[d];
    g_xg_tab[c * G4C + t] = acc;
}

// ---------------- Kp: transpose word weights to k-major ----------------
__global__ void prep_kernel(const float* __restrict__ Wih_w,
                            const float* __restrict__ Whh_w) {
    int idx = blockIdx.x * blockDim.x + threadIdx.x;
    if (idx < (KW/4) * G4W * 4) {     // 393216
        int j  = idx & 3;
        int g  = (idx >> 2) & 1023;
        int k4 = idx >> 12;
        int k  = k4 * 4 + j;          // 0..383
        g_WcatT[idx] = (k < HC_) ? Wih_w[g * (D_ + HC_) + D_ + k]
                                 : Whh_w[g * H_ + (k - HC_)];
    }
    if (idx < (D_/4) * G4W * 4) {     // 262144
        int j  = idx & 3;
        int g  = (idx >> 2) & 1023;
        int k4 = idx >> 12;
        int k  = k4 * 4 + j;          // 0..255
        g_WweT[idx] = Wih_w[g * (D_ + HC_) + k];
    }
}

// ---------------- K1: wg[s] = we_s @ Wih_w[:, :D].T + b_w (8 words/block) ----------------
__global__ __launch_bounds__(256) void wg_kernel(const int* __restrict__ sentence,
                                                 const float* __restrict__ word_emb,
                                                 const float* __restrict__ b_w) {
    __shared__ float sh_we[8 * D_];
    __shared__ int   sh_s[8];
    const int t = threadIdx.x;                 // 256
    const int s0 = blockIdx.x * 8;             // 1024 blocks
    if (t < 8) sh_s[t] = sentence[s0 + t];
    __syncthreads();
    for (int i = t; i < 8 * D_; i += 256) {
        int w = i >> 8, d = i & (D_ - 1);
        sh_we[i] = word_emb[(long long)sh_s[w] * D_ + d];
    }
    __syncthreads();

    float acc[4][8];
#pragma unroll
    for (int q = 0; q < 4; ++q)
#pragma unroll
        for (int w = 0; w < 8; ++w) acc[q][w] = 0.f;

    const float4* WT  = (const float4*)g_WweT;   // [k4][1024]
    const float4* we4 = (const float4*)sh_we;    // [w][64]
    for (int k4 = 0; k4 < D_/4; ++k4) {
        float4 wv[4];
#pragma unroll
        for (int q = 0; q < 4; ++q) wv[q] = WT[k4 * G4W + q * 256 + t];
#pragma unroll
        for (int w = 0; w < 8; ++w) {
            float4 xv = we4[w * (D_/4) + k4];
#pragma unroll
            for (int q = 0; q < 4; ++q)
                acc[q][w] += wv[q].x * xv.x + wv[q].y * xv.y +
                             wv[q].z * xv.z + wv[q].w * xv.w;
        }
    }
#pragma unroll
    for (int q = 0; q < 4; ++q) {
        float bb = b_w[q * 256 + t];
#pragma unroll
        for (int w = 0; w < 8; ++w)
            g_wg[(s0 + w) * G4W + q * 256 + t] = acc[q][w] + bb;
    }
}

// ---------------- K2: the sequential scan (single CTA) ----------------
// smem layout (dynamic):
//   [0      , 65536)  sh_wc : ull[16][512]  (Whh_c k=96..127, pair-major)
//   [65536  , 67072)  sh_x  : float[384]    (hc | hw)
//   [67072  , 71168)  sh_g  : float[1024]
//   [71168  , 88576)  sh_wout: float[17*256]
//   [88576  , 88704)  sh_bout: float[17]
//   [88704  , 88832)  sh_ch : int[17] (16 chars + len)
#define SMEM_BYTES 90112

__global__ __launch_bounds__(512, 1) void seq_kernel(
    const int*   __restrict__ word_chars,
    const int*   __restrict__ char_lens,
    const float* __restrict__ Whh_c,
    const float* __restrict__ Wout,
    const float* __restrict__ bout,
    float*       __restrict__ out) {

    extern __shared__ unsigned char smraw[];
    ull*   sh_wc   = (ull*)smraw;
    float* sh_x    = (float*)(smraw + 65536);
    float* sh_g    = (float*)(smraw + 67072);
    float* sh_wout = (float*)(smraw + 71168);
    float* sh_bout = (float*)(smraw + 88576);
    int*   sh_ch   = (int*)(smraw + 88704);

    const int t = threadIdx.x;    // 512

    // Register-resident Whh_c row t, k = 0..95 (48 packed pairs);
    // k = 96..127 goes to smem, pair-major so loads are conflict-free.
    ull wr[48];
    {
        const ull* wrow = (const ull*)(Whh_c + t * HC_);   // 512B-aligned row
#pragma unroll
        for (int i = 0; i < 48; ++i) wr[i] = wrow[i];
#pragma unroll
        for (int i = 0; i < 16; ++i) sh_wc[i * 512 + t] = wrow[48 + i];
    }
    for (int i = t; i < T_ * H_; i += 512) sh_wout[i] = Wout[i];
    if (t < T_) sh_bout[t] = bout[t];
    for (int i = t; i < KW; i += 512) sh_x[i] = 0.f;
    float ccr = 0.f;   // cell state, char LSTM  (owned by t<128)
    float cwr = 0.f;   // cell state, word LSTM  (owned by t<256)
    __syncthreads();

    const ulonglong2* hp = (const ulonglong2*)sh_x;      // 96 x 16B over [hc|hw]
    const ulonglong2* Wp = (const ulonglong2*)g_WcatT;   // [k4][1024]

    for (int s = 0; s < S_; ++s) {
        if (t < LC_)  sh_ch[t]  = word_chars[s * LC_ + t];
        if (t == LC_) sh_ch[LC_] = char_lens[s];
        __syncthreads();
        const int len = sh_ch[LC_];

        // -------- char LSTM steps (skip frozen t >= len steps) --------
        for (int ct = 0; ct < len; ++ct) {
            const int ch = sh_ch[ct];
            float xg = g_xg_tab[ch * G4C + t];   // L2-hot, hoisted load
            ull a0 = 0, a1 = 0;
#pragma unroll
            for (int i = 0; i < 24; ++i) {       // k = 0..95 from registers
                ulonglong2 hv = hp[i];
                fma2(a0, wr[2 * i],     hv.x);
                fma2(a1, wr[2 * i + 1], hv.y);
            }
#pragma unroll
            for (int i = 0; i < 8; ++i) {        // k = 96..127 from smem
                ulonglong2 hv = hp[24 + i];
                fma2(a0, sh_wc[(2 * i) * 512 + t],     hv.x);
                fma2(a1, sh_wc[(2 * i + 1) * 512 + t], hv.y);
            }
            sh_g[t] = xg + redu(a0) + redu(a1);
            __syncthreads();
            if (t < HC_) {
                float gi = sigf(sh_g[t]);
                float gf = sigf(sh_g[HC_ + t]);
                float gg = tanh_(sh_g[2 * HC_ + t]);
                float go = sigf(sh_g[3 * HC_ + t]);
                ccr = gf * ccr + gi * gg;
                sh_x[t] = go * tanh_(ccr);
            }
            __syncthreads();
        }

        // -------- word LSTM step --------
        float wgl0 = g_wg[s * G4W + t];          // we-part + bias, precomputed
        float wgl1 = g_wg[s * G4W + 512 + t];
        ull b0 = 0, b1 = 0, b2 = 0, b3 = 0;
#pragma unroll 4
        for (int i = 0; i < KW/4; ++i) {         // 96 iterations over [hc|hw]
            ulonglong2 xv = hp[i];
            ulonglong2 wa = Wp[i * G4W + t];
            ulonglong2 wb = Wp[i * G4W + 512 + t];
            fma2(b0, wa.x, xv.x);  fma2(b1, wa.y, xv.y);
            fma2(b2, wb.x, xv.x);  fma2(b3, wb.y, xv.y);
        }
        sh_g[t]       = wgl0 + redu(b0) + redu(b1);
        sh_g[512 + t] = wgl1 + redu(b2) + redu(b3);
        __syncthreads();
        if (t < H_) {
            float gi = sigf(sh_g[t]);
            float gf = sigf(sh_g[H_ + t]);
            float gg = tanh_(sh_g[2 * H_ + t]);
            float go = sigf(sh_g[3 * H_ + t]);
            cwr = gf * cwr + gi * gg;
            sh_x[HC_ + t] = go * tanh_(cwr);
        }
        __syncthreads();

        // -------- logits: 17 outputs x 16 threads each --------
        {
            int o = t >> 4; if (o > 16) o = 16;   // clamp so all lanes stay converged
            int l16 = t & 15;
            const float4* wo4 = (const float4*)sh_wout;        // [17][64]
            const float4* xw4 = (const float4*)(sh_x + HC_);   // hw as [64] float4
            float acc = 0.f;
#pragma unroll
            for (int j = 0; j < 4; ++j) {
                float4 w  = wo4[o * (H_/4) + l16 * 4 + j];
                float4 xv = xw4[l16 * 4 + j];
                acc += w.x * xv.x + w.y * xv.y + w.z * xv.z + w.w * xv.w;
            }
            acc += __shfl_xor_sync(0xffffffffu, acc, 8);
            acc += __shfl_xor_sync(0xffffffffu, acc, 4);
            acc += __shfl_xor_sync(0xffffffffu, acc, 2);
            acc += __shfl_xor_sync(0xffffffffu, acc, 1);
            if (t < T_ * 16 && l16 == 0) out[s * T_ + o] = acc + sh_bout[o];
        }
        __syncthreads();
    }
}

// ---------------- launch ----------------
extern "C" void kernel_launch(void* const* d_in, const int* in_sizes, int n_in,
                              void* d_out, int out_size) {
    const int*   sentence   = (const int*)  d_in[0];
    const int*   word_chars = (const int*)  d_in[1];
    const int*   char_lens  = (const int*)  d_in[2];
    const float* word_emb   = (const float*)d_in[3];
    const float* char_emb   = (const float*)d_in[4];
    const float* Wih_c      = (const float*)d_in[5];
    const float* Whh_c      = (const float*)d_in[6];
    const float* b_c        = (const float*)d_in[7];
    const float* Wih_w      = (const float*)d_in[8];
    const float* Whh_w      = (const float*)d_in[9];
    const float* b_w        = (const float*)d_in[10];
    const float* Wout       = (const float*)d_in[11];
    const float* bout       = (const float*)d_in[12];
    float* out = (float*)d_out;

    (void)in_sizes; (void)n_in; (void)out_size;

    prep_kernel<<<1536, 256>>>(Wih_w, Whh_w);
    xg_kernel<<<CV_, G4C>>>(Wih_c, char_emb, b_c);
    wg_kernel<<<S_ / 8, 256>>>(sentence, word_emb, b_w);

    cudaFuncSetAttribute(seq_kernel,
                         cudaFuncAttributeMaxDynamicSharedMemorySize, SMEM_BYTES);
    seq_kernel<<<1, 512, SMEM_BYTES>>>(word_chars, char_lens, Whh_c, Wout, bout, out);
}

// round 13
// speedup vs baseline: 1.9900x; 1.9900x over previous
#include <cuda_runtime.h>
#include <cuda_bf16.h>

// Problem constants
#define S_   8192
#define LC_  16
#define D_   256
#define CV_  128
#define DC_  64
#define HC_  128
#define H_   256
#define T_   17
// derived
#define G4C  (4*HC_)        // 512 char gates
#define G4W  (4*H_)         // 1024 word gates
#define KW   (HC_ + H_)     // 384 recurrent-x length for word LSTM
#define NCTA 8              // cluster: CTA0 = char/orchestrator, 1..7 = word workers

typedef unsigned long long ull;

// ---------------- device scratch (no allocation allowed) ----------------
__device__ __align__(16) float g_xg_tab[CV_ * G4C];        // 256 KB: per-char input gates
__device__ __align__(16) float g_wg[S_ * G4W];             // 32 MB : word-emb gate contributions (+b_w)
__device__ __align__(16) float g_WweT[(D_/4) * G4W * 4];   // 1 MB  : k-major we-part weights
__device__ __align__(16) ull   g_Wreg[7 * 512 * 48];       // 1.3 MB: per-thread register word-weight slices
__device__ __align__(16) ull   g_Wss [7 * 3840];           // 210 KB: per-worker smem-gate slices (pad 20)

// ---------------- helpers ----------------
__device__ __forceinline__ void fma2(ull &acc, ull a, ull b) {
    asm("fma.rn.f32x2 %0, %1, %2, %0;" : "+l"(acc) : "l"(a), "l"(b));
}
__device__ __forceinline__ float redu(ull a) {
    return __uint_as_float((unsigned)(a & 0xffffffffull)) +
           __uint_as_float((unsigned)(a >> 32));
}
__device__ __forceinline__ float sigf(float x) {
    return __fdividef(1.0f, 1.0f + __expf(-x));
}
__device__ __forceinline__ float tanh_(float x) {
    float e = __expf(-2.0f * fabsf(x));
    float r = __fdividef(1.0f - e, 1.0f + e);
    return copysignf(r, x);
}
__device__ __forceinline__ unsigned smem_u32(const void* p) {
    unsigned a;
    asm("{ .reg .u64 t; cvta.to.shared.u64 t, %1; cvt.u32.u64 %0, t; }" : "=r"(a) : "l"(p));
    return a;
}
__device__ __forceinline__ unsigned ctarank() {
    unsigned r; asm("mov.u32 %0, %%cluster_ctarank;" : "=r"(r)); return r;
}
__device__ __forceinline__ unsigned mapa0(unsigned a) {
    unsigned r; asm("mapa.shared::cluster.u32 %0, %1, %2;" : "=r"(r) : "r"(a), "r"(0u)); return r;
}
__device__ __forceinline__ ull ld_dsm_u64(unsigned a) {
    ull v; asm volatile("ld.shared::cluster.b64 %0, [%1];" : "=l"(v) : "r"(a)); return v;
}
__device__ __forceinline__ void st_dsm_f32(unsigned a, float v) {
    asm volatile("st.shared::cluster.f32 [%0], %1;" :: "r"(a), "f"(v));
}
__device__ __forceinline__ void cbar_arrive() {
    asm volatile("barrier.cluster.arrive.aligned;" ::: "memory");
}
__device__ __forceinline__ void cbar_wait() {
    asm volatile("barrier.cluster.wait.aligned;" ::: "memory");
}
__device__ __forceinline__ ull packf2(float lo, float hi) {
    return (ull)__float_as_uint(lo) | ((ull)__float_as_uint(hi) << 32);
}

// ---------------- K0: per-char gate table ----------------
__global__ void xg_kernel(const float* __restrict__ Wih_c,
                          const float* __restrict__ char_emb,
                          const float* __restrict__ b_c) {
    __shared__ float ce[DC_];
    const int c = blockIdx.x, t = threadIdx.x;   // 128 blocks x 512 threads
    if (t < DC_) ce[t] = char_emb[c * DC_ + t];
    __syncthreads();
    float acc = b_c[t];
#pragma unroll
    for (int d = 0; d < DC_; ++d) acc += Wih_c[t * DC_ + d] * ce[d];
    g_xg_tab[c * G4C + t] = acc;
}

// ---------------- Kp: k-major we-part weights for the wg GEMM ----------------
__global__ void prep_kernel(const float* __restrict__ Wih_w) {
    int idx = blockIdx.x * blockDim.x + threadIdx.x;
    if (idx < (D_/4) * G4W * 4) {     // 262144
        int j  = idx & 3;
        int g  = (idx >> 2) & 1023;
        int k4 = idx >> 12;
        int k  = k4 * 4 + j;
        g_WweT[idx] = Wih_w[g * (D_ + HC_) + k];
    }
}

// ---------------- Ks: stage the recurrent word weights into cluster slices ----------------
// x for the word LSTM = [hc(128) | hw(256)]; Wx(g,k) = k<128 ? Wih_w[g][D+k] : Whh_w[g][k-128].
// Reg slices (workers 1..7): gate g = r1*128 + (t>>2), thread quarter q = t&3 owns k = q*96..q*96+95
//   stored as pairs: g_Wreg[r1*24576 + j*512 + t], j=0..47 -> (Wx(g,q*96+2j), Wx(g,q*96+2j+1)).
// Smem slices: gates 896..1023, worker r1 gets n_s = 19(r1<2) else 18, layout [p][gl(pad20)] pairs.
__global__ void slc_kernel(const float* __restrict__ Wih_w,
                           const float* __restrict__ Whh_w) {
    const int NREG = 7 * 512 * 48;   // 172032
    const int NSS  = 7 * 3840;       // 26880
    int idx = blockIdx.x * blockDim.x + threadIdx.x;
    int g, k;
    ull* dst;
    if (idx < NREG) {
        int r1  = idx / (512 * 48);
        int rem = idx % (512 * 48);
        int j = rem / 512, t = rem % 512;
        int il = t >> 2, q = t & 3;
        g = r1 * 128 + il;            // 0..895
        k = q * 96 + 2 * j;
        dst = g_Wreg + idx;
    } else if (idx < NREG + NSS) {
        int e  = idx - NREG;
        int r1 = e / 3840;
        int o  = e % 3840;
        int p = o / 20, gl = o % 20;
        int n_s = 18 + (r1 < 2 ? 1 : 0);
        dst = g_Wss + e;
        if (gl >= n_s) { *dst = 0; return; }
        g = 896 + r1 * 18 + (r1 < 2 ? r1 : 2) + gl;   // 896..1023
        k = 2 * p;
    } else return;
    float v0 = (k     < HC_) ? Wih_w[g * (D_ + HC_) + D_ + k]     : Whh_w[g * H_ + (k     - HC_)];
    float v1 = (k + 1 < HC_) ? Wih_w[g * (D_ + HC_) + D_ + k + 1] : Whh_w[g * H_ + (k + 1 - HC_)];
    *dst = packf2(v0, v1);
}

// ---------------- K1: wg[s] = we_s @ Wih_w[:, :D].T + b_w (8 words/block) ----------------
__global__ __launch_bounds__(256) void wg_kernel(const int* __restrict__ sentence,
                                                 const float* __restrict__ word_emb,
                                                 const float* __restrict__ b_w) {
    __shared__ float sh_we[8 * D_];
    __shared__ int   sh_s[8];
    const int t = threadIdx.x;
    const int s0 = blockIdx.x * 8;
    if (t < 8) sh_s[t] = sentence[s0 + t];
    __syncthreads();
    for (int i = t; i < 8 * D_; i += 256) {
        int w = i >> 8, d = i & (D_ - 1);
        sh_we[i] = word_emb[(long long)sh_s[w] * D_ + d];
    }
    __syncthreads();

    float acc[4][8];
#pragma unroll
    for (int q = 0; q < 4; ++q)
#pragma unroll
        for (int w = 0; w < 8; ++w) acc[q][w] = 0.f;

    const float4* WT  = (const float4*)g_WweT;
    const float4* we4 = (const float4*)sh_we;
    for (int k4 = 0; k4 < D_/4; ++k4) {
        float4 wv[4];
#pragma unroll
        for (int q = 0; q < 4; ++q) wv[q] = WT[k4 * G4W + q * 256 + t];
#pragma unroll
        for (int w = 0; w < 8; ++w) {
            float4 xv = we4[w * (D_/4) + k4];
#pragma unroll
            for (int q = 0; q < 4; ++q)
                acc[q][w] += wv[q].x * xv.x + wv[q].y * xv.y +
                             wv[q].z * xv.z + wv[q].w * xv.w;
        }
    }
#pragma unroll
    for (int q = 0; q < 4; ++q) {
        float bb = b_w[q * 256 + t];
#pragma unroll
        for (int w = 0; w < 8; ++w)
            g_wg[(s0 + w) * G4W + q * 256 + t] = acc[q][w] + bb;
    }
}

// ---------------- K2: sequential scan over an 8-CTA cluster ----------------
// CTA0 smem:
#define O_WC   0         // ull[16][512] char Whh k=96..127 (65536 B)
#define O_X    65536     // float[384]  x = [hc | hw]             (1536 B)
#define O_G    67072     // float[512]  char gates               (2048 B)
#define O_GW   69120     // float[1024] word gate dots (DSMEM target, 4096 B)
#define O_WOUT 73216     // float[17*256]                        (17408 B)
#define O_BOUT 90624     // float[17]                            (128 B)
#define O_CH   90752     // int[17]                              (128 B)
// worker smem:
#define O_WSS  0         // ull[3840]  smem-gate weights          (30720 B)
#define O_XQ2  30720     // ull[4][52] per-quarter padded x pairs (1664 B)
#define O_XLIN 32384     // ull[192]   linear x pairs             (1536 B)
#define SMEM_BYTES 92160

__global__ __launch_bounds__(512, 1) __cluster_dims__(NCTA, 1, 1)
void seq_kernel(const int*   __restrict__ word_chars,
                const int*   __restrict__ char_lens,
                const float* __restrict__ Whh_c,
                const float* __restrict__ Wout,
                const float* __restrict__ bout,
                float*       __restrict__ out) {

    extern __shared__ unsigned char smraw[];
    const int t = threadIdx.x;                 // 512
    const unsigned rank  = ctarank();
    const unsigned sbase = smem_u32(smraw);

    if (rank == 0) {
        // ================= char CTA + orchestrator =================
        ull*   sh_wc   = (ull*)(smraw + O_WC);
        float* sh_x    = (float*)(smraw + O_X);
        float* sh_g    = (float*)(smraw + O_G);
        float* sh_gw   = (float*)(smraw + O_GW);
        float* sh_wout = (float*)(smraw + O_WOUT);
        float* sh_bout = (float*)(smraw + O_BOUT);
        int*   sh_ch   = (int*)(smraw + O_CH);

        // char Whh row t: k=0..95 in regs (48 pairs), k=96..127 in smem pair-major
        ull wr[48];
        {
            const ull* wrow = (const ull*)(Whh_c + t * HC_);
#pragma unroll
            for (int i = 0; i < 48; ++i) wr[i] = wrow[i];
#pragma unroll
            for (int i = 0; i < 16; ++i) sh_wc[i * 512 + t] = wrow[48 + i];
        }
        for (int i = t; i < T_ * H_; i += 512) sh_wout[i] = Wout[i];
        if (t < T_) sh_bout[t] = bout[t];
        for (int i = t; i < KW; i += 512) sh_x[i] = 0.f;
        float ccr = 0.f;   // char cell (t<128)
        float cwr = 0.f;   // word cell (t<256)
        __syncthreads();

        const ulonglong2* hp = (const ulonglong2*)sh_x;

        for (int s = 0; s < S_; ++s) {
            if (t < LC_)  sh_ch[t]   = word_chars[s * LC_ + t];
            if (t == LC_) sh_ch[LC_] = char_lens[s];
            float wgl0, wgl1, wgl2, wgl3;   // prefetch g_wg early (hidden behind char phase)
            if (t < H_) {
                wgl0 = g_wg[s * G4W + t];
                wgl1 = g_wg[s * G4W + 256 + t];
                wgl2 = g_wg[s * G4W + 512 + t];
                wgl3 = g_wg[s * G4W + 768 + t];
            }
            __syncthreads();
            const int len = sh_ch[LC_];

            // -------- char LSTM steps (frozen t>=len steps skipped) --------
            for (int ct = 0; ct < len; ++ct) {
                const int ch = sh_ch[ct];
                float xg = g_xg_tab[ch * G4C + t];
                ull a0 = 0, a1 = 0;
#pragma unroll
                for (int i = 0; i < 24; ++i) {
                    ulonglong2 hv = hp[i];
                    fma2(a0, wr[2 * i],     hv.x);
                    fma2(a1, wr[2 * i + 1], hv.y);
                }
#pragma unroll
                for (int i = 0; i < 8; ++i) {
                    ulonglong2 hv = hp[24 + i];
                    fma2(a0, sh_wc[(2 * i) * 512 + t],     hv.x);
                    fma2(a1, sh_wc[(2 * i + 1) * 512 + t], hv.y);
                }
                sh_g[t] = xg + redu(a0) + redu(a1);
                __syncthreads();
                if (t < HC_) {
                    float gi = sigf(sh_g[t]);
                    float gf = sigf(sh_g[HC_ + t]);
                    float gg = tanh_(sh_g[2 * HC_ + t]);
                    float go = sigf(sh_g[3 * HC_ + t]);
                    ccr = gf * ccr + gi * gg;
                    sh_x[t] = go * tanh_(ccr);
                }
                __syncthreads();
            }

            // -------- word LSTM: x published to workers, gates come back --------
            cbar_arrive(); cbar_wait();     // A: x = [hc|hw] ready for workers
            cbar_arrive(); cbar_wait();     // B: sh_gw filled by workers

            if (t < H_) {
                float gi = sigf(wgl0 + sh_gw[t]);
                float gf = sigf(wgl1 + sh_gw[256 + t]);
                float gg = tanh_(wgl2 + sh_gw[512 + t]);
                float go = sigf(wgl3 + sh_gw[768 + t]);
                cwr = gf * cwr + gi * gg;
                sh_x[HC_ + t] = go * tanh_(cwr);
            }
            __syncthreads();

            // -------- logits: 17 outputs x 16 threads --------
            {
                int o = t >> 4; if (o > 16) o = 16;
                int l16 = t & 15;
                const float4* wo4 = (const float4*)sh_wout;
                const float4* xw4 = (const float4*)(sh_x + HC_);
                float acc = 0.f;
#pragma unroll
                for (int j = 0; j < 4; ++j) {
                    float4 w  = wo4[o * (H_/4) + l16 * 4 + j];
                    float4 xv = xw4[l16 * 4 + j];
                    acc += w.x * xv.x + w.y * xv.y + w.z * xv.z + w.w * xv.w;
                }
                acc += __shfl_xor_sync(0xffffffffu, acc, 8);
                acc += __shfl_xor_sync(0xffffffffu, acc, 4);
                acc += __shfl_xor_sync(0xffffffffu, acc, 2);
                acc += __shfl_xor_sync(0xffffffffu, acc, 1);
                if (t < T_ * 16 && l16 == 0) out[s * T_ + o] = acc + sh_bout[o];
            }
            __syncthreads();
        }
        cbar_arrive(); cbar_wait();         // final drain
    } else {
        // ================= word-gate worker CTA =================
        ull* wss  = (ull*)(smraw + O_WSS);
        ull* xq2  = (ull*)(smraw + O_XQ2);
        ull* xlin = (ull*)(smraw + O_XLIN);
        const int r1  = (int)rank - 1;
        const int n_s = 18 + (r1 < 2 ? 1 : 0);
        const int gbase_s = 896 + r1 * 18 + (r1 < 2 ? r1 : 2);

        // register-resident weight slice: gate (r1*128 + t>>2), k quarter (t&3)
        ull wr[48];
#pragma unroll
        for (int j = 0; j < 48; ++j) wr[j] = g_Wreg[r1 * 24576 + j * 512 + t];
        for (int i = t; i < 3840; i += 512) wss[i] = g_Wss[r1 * 3840 + i];
        __syncthreads();

        const int il = t >> 2, q = t & 3;
        const int greg = r1 * 128 + il;                      // global gate of reg slice
        const unsigned x_rem  = mapa0(sbase + O_X);          // CTA0 sh_x
        const unsigned gw_rem = mapa0(sbase + O_GW);         // CTA0 sh_gw
        const ulonglong2* xqp = (const ulonglong2*)(xq2 + q * 52);
        const int glc = (t >> 4) < n_s ? (t >> 4) : (n_s - 1);  // clamped smem-gate id
        const int l16 = t & 15;

        for (int s = 0; s < S_; ++s) {
            cbar_arrive(); cbar_wait();    // A: x ready on CTA0
            if (t < 192) {                 // pull x pairs via DSMEM, stage two layouts
                ull v = ld_dsm_u64(x_rem + t * 8);
                int qq = t / 48, jj = t % 48;
                xq2[qq * 52 + jj] = v;
                xlin[t] = v;
            }
            __syncthreads();

            // reg gates: 96 k's per thread, 4 threads/gate
            ull a0 = 0, a1 = 0;
#pragma unroll
            for (int j2 = 0; j2 < 24; ++j2) {
                ulonglong2 xv = xqp[j2];
                fma2(a0, wr[2 * j2],     xv.x);
                fma2(a1, wr[2 * j2 + 1], xv.y);
            }
            float acc = redu(a0) + redu(a1);
            acc += __shfl_xor_sync(0xffffffffu, acc, 1);
            acc += __shfl_xor_sync(0xffffffffu, acc, 2);
            if (q == 0) st_dsm_f32(gw_rem + greg * 4, acc);

            // smem gates: 16 threads/gate, 24 k's each (all lanes run; store guarded)
            {
                ull a = 0;
#pragma unroll
                for (int jj = 0; jj < 12; ++jj) {
                    int p = jj * 16 + l16;
                    fma2(a, wss[p * 20 + glc], xlin[p]);
                }
                float a2 = redu(a);
                a2 += __shfl_xor_sync(0xffffffffu, a2, 1);
                a2 += __shfl_xor_sync(0xffffffffu, a2, 2);
                a2 += __shfl_xor_sync(0xffffffffu, a2, 4);
                a2 += __shfl_xor_sync(0xffffffffu, a2, 8);
                if (l16 == 0 && (t >> 4) < n_s)
                    st_dsm_f32(gw_rem + (gbase_s + glc) * 4, a2);
            }
            cbar_arrive(); cbar_wait();    // B: results delivered
        }
        cbar_arrive(); cbar_wait();        // final drain
    }
}

// ---------------- launch ----------------
extern "C" void kernel_launch(void* const* d_in, const int* in_sizes, int n_in,
                              void* d_out, int out_size) {
    const int*   sentence   = (const int*)  d_in[0];
    const int*   word_chars = (const int*)  d_in[1];
    const int*   char_lens  = (const int*)  d_in[2];
    const float* word_emb   = (const float*)d_in[3];
    const float* char_emb   = (const float*)d_in[4];
    const float* Wih_c      = (const float*)d_in[5];
    const float* Whh_c      = (const float*)d_in[6];
    const float* b_c        = (const float*)d_in[7];
    const float* Wih_w      = (const float*)d_in[8];
    const float* Whh_w      = (const float*)d_in[9];
    const float* b_w        = (const float*)d_in[10];
    const float* Wout       = (const float*)d_in[11];
    const float* bout       = (const float*)d_in[12];
    float* out = (float*)d_out;

    (void)in_sizes; (void)n_in; (void)out_size;

    prep_kernel<<<1024, 256>>>(Wih_w);
    slc_kernel<<<777, 256>>>(Wih_w, Whh_w);
    xg_kernel<<<CV_, G4C>>>(Wih_c, char_emb, b_c);
    wg_kernel<<<S_ / 8, 256>>>(sentence, word_emb, b_w);

    cudaFuncSetAttribute(seq_kernel,
                         cudaFuncAttributeMaxDynamicSharedMemorySize, SMEM_BYTES);
    seq_kernel<<<NCTA, 512, SMEM_BYTES>>>(word_chars, char_lens, Whh_c, Wout, bout, out);
}

// round 14
// speedup vs baseline: 2.0917x; 1.0511x over previous
#include <cuda_runtime.h>
#include <cuda_bf16.h>

// Problem constants
#define S_   8192
#define LC_  16
#define D_   256
#define CV_  128
#define DC_  64
#define HC_  128
#define H_   256
#define T_   17
// derived
#define G4C  (4*HC_)        // 512 char gates
#define G4W  (4*H_)         // 1024 word gates
#define KW   (HC_ + H_)     // 384 recurrent-x length for word LSTM
#define NCTA 8              // cluster: CTA0 = char/orchestrator, 1..7 = word workers

typedef unsigned long long ull;

// ---------------- device scratch (no allocation allowed) ----------------
__device__ __align__(16) float g_xg_tab[CV_ * G4C];        // 256 KB: per-char input gates
__device__ __align__(16) float g_wg[S_ * G4W];             // 32 MB : word-emb gate contributions (+b_w)
__device__ __align__(16) float g_WweT[(D_/4) * G4W * 4];   // 1 MB  : k-major we-part weights
__device__ __align__(16) ull   g_Wreg[7 * 512 * 48];       // 1.3 MB: per-thread register word-weight slices
__device__ __align__(16) ull   g_Wss [7 * 3840];           // 210 KB: per-worker smem-gate slices (pad 20)
__device__ __align__(16) ull   g_xbuf[192];                // 1.5 KB: x = [hc|hw] broadcast via L2

// ---------------- helpers ----------------
__device__ __forceinline__ void fma2(ull &acc, ull a, ull b) {
    asm("fma.rn.f32x2 %0, %1, %2, %0;" : "+l"(acc) : "l"(a), "l"(b));
}
__device__ __forceinline__ float redu(ull a) {
    return __uint_as_float((unsigned)(a & 0xffffffffull)) +
           __uint_as_float((unsigned)(a >> 32));
}
__device__ __forceinline__ float sigf(float x) {
    return __fdividef(1.0f, 1.0f + __expf(-x));
}
__device__ __forceinline__ float tanh_(float x) {
    float e = __expf(-2.0f * fabsf(x));
    float r = __fdividef(1.0f - e, 1.0f + e);
    return copysignf(r, x);
}
__device__ __forceinline__ unsigned smem_u32(const void* p) {
    unsigned a;
    asm("{ .reg .u64 t; cvta.to.shared.u64 t, %1; cvt.u32.u64 %0, t; }" : "=r"(a) : "l"(p));
    return a;
}
__device__ __forceinline__ unsigned ctarank() {
    unsigned r; asm("mov.u32 %0, %%cluster_ctarank;" : "=r"(r)); return r;
}
__device__ __forceinline__ unsigned mapa0(unsigned a) {
    unsigned r; asm("mapa.shared::cluster.u32 %0, %1, %2;" : "=r"(r) : "r"(a), "r"(0u)); return r;
}
__device__ __forceinline__ void st_dsm_f32(unsigned a, float v) {
    asm volatile("st.shared::cluster.f32 [%0], %1;" :: "r"(a), "f"(v));
}
__device__ __forceinline__ void cbar_arrive() {
    asm volatile("barrier.cluster.arrive.aligned;" ::: "memory");
}
__device__ __forceinline__ void cbar_wait() {
    asm volatile("barrier.cluster.wait.aligned;" ::: "memory");
}
__device__ __forceinline__ ull packf2(float lo, float hi) {
    return (ull)__float_as_uint(lo) | ((ull)__float_as_uint(hi) << 32);
}
__device__ __forceinline__ ull ldcg_u64(const ull* p) {
    ull v; asm volatile("ld.global.cg.b64 %0, [%1];" : "=l"(v) : "l"(p)); return v;
}
__device__ __forceinline__ void stcg_u64(ull* p, ull v) {
    asm volatile("st.global.cg.b64 [%0], %1;" :: "l"(p), "l"(v));
}

// ---------------- K0: per-char gate table ----------------
__global__ void xg_kernel(const float* __restrict__ Wih_c,
                          const float* __restrict__ char_emb,
                          const float* __restrict__ b_c) {
    __shared__ float ce[DC_];
    const int c = blockIdx.x, t = threadIdx.x;   // 128 blocks x 512 threads
    if (t < DC_) ce[t] = char_emb[c * DC_ + t];
    __syncthreads();
    float acc = b_c[t];
#pragma unroll
    for (int d = 0; d < DC_; ++d) acc += Wih_c[t * DC_ + d] * ce[d];
    g_xg_tab[c * G4C + t] = acc;
}

// ---------------- Kp: k-major we-part weights for the wg GEMM ----------------
__global__ void prep_kernel(const float* __restrict__ Wih_w) {
    int idx = blockIdx.x * blockDim.x + threadIdx.x;
    if (idx < (D_/4) * G4W * 4) {     // 262144
        int j  = idx & 3;
        int g  = (idx >> 2) & 1023;
        int k4 = idx >> 12;
        int k  = k4 * 4 + j;
        g_WweT[idx] = Wih_w[g * (D_ + HC_) + k];
    }
}

// ---------------- Ks: stage the recurrent word weights into cluster slices ----------------
// x for the word LSTM = [hc(128) | hw(256)]; Wx(g,k) = k<128 ? Wih_w[g][D+k] : Whh_w[g][k-128].
// Reg slices (workers 1..7): gate g = r1*128 + (t>>2), thread quarter q = t&3 owns k = q*96..q*96+95
//   stored as pairs: g_Wreg[r1*24576 + j*512 + t], j=0..47 -> (Wx(g,q*96+2j), Wx(g,q*96+2j+1)).
// Smem slices: gates 896..1023, worker r1 gets n_s = 19(r1<2) else 18, layout [p][gl(pad20)] pairs.
__global__ void slc_kernel(const float* __restrict__ Wih_w,
                           const float* __restrict__ Whh_w) {
    const int NREG = 7 * 512 * 48;   // 172032
    const int NSS  = 7 * 3840;       // 26880
    int idx = blockIdx.x * blockDim.x + threadIdx.x;
    int g, k;
    ull* dst;
    if (idx < NREG) {
        int r1  = idx / (512 * 48);
        int rem = idx % (512 * 48);
        int j = rem / 512, t = rem % 512;
        int il = t >> 2, q = t & 3;
        g = r1 * 128 + il;            // 0..895
        k = q * 96 + 2 * j;
        dst = g_Wreg + idx;
    } else if (idx < NREG + NSS) {
        int e  = idx - NREG;
        int r1 = e / 3840;
        int o  = e % 3840;
        int p = o / 20, gl = o % 20;
        int n_s = 18 + (r1 < 2 ? 1 : 0);
        dst = g_Wss + e;
        if (gl >= n_s) { *dst = 0; return; }
        g = 896 + r1 * 18 + (r1 < 2 ? r1 : 2) + gl;   // 896..1023
        k = 2 * p;
    } else return;
    float v0 = (k     < HC_) ? Wih_w[g * (D_ + HC_) + D_ + k]     : Whh_w[g * H_ + (k     - HC_)];
    float v1 = (k + 1 < HC_) ? Wih_w[g * (D_ + HC_) + D_ + k + 1] : Whh_w[g * H_ + (k + 1 - HC_)];
    *dst = packf2(v0, v1);
}

// ---------------- K1: wg[s] = we_s @ Wih_w[:, :D].T + b_w (8 words/block) ----------------
__global__ __launch_bounds__(256) void wg_kernel(const int* __restrict__ sentence,
                                                 const float* __restrict__ word_emb,
                                                 const float* __restrict__ b_w) {
    __shared__ float sh_we[8 * D_];
    __shared__ int   sh_s[8];
    const int t = threadIdx.x;
    const int s0 = blockIdx.x * 8;
    if (t < 8) sh_s[t] = sentence[s0 + t];
    __syncthreads();
    for (int i = t; i < 8 * D_; i += 256) {
        int w = i >> 8, d = i & (D_ - 1);
        sh_we[i] = word_emb[(long long)sh_s[w] * D_ + d];
    }
    __syncthreads();

    float acc[4][8];
#pragma unroll
    for (int q = 0; q < 4; ++q)
#pragma unroll
        for (int w = 0; w < 8; ++w) acc[q][w] = 0.f;

    const float4* WT  = (const float4*)g_WweT;
    const float4* we4 = (const float4*)sh_we;
    for (int k4 = 0; k4 < D_/4; ++k4) {
        float4 wv[4];
#pragma unroll
        for (int q = 0; q < 4; ++q) wv[q] = WT[k4 * G4W + q * 256 + t];
#pragma unroll
        for (int w = 0; w < 8; ++w) {
            float4 xv = we4[w * (D_/4) + k4];
#pragma unroll
            for (int q = 0; q < 4; ++q)
                acc[q][w] += wv[q].x * xv.x + wv[q].y * xv.y +
                             wv[q].z * xv.z + wv[q].w * xv.w;
        }
    }
#pragma unroll
    for (int q = 0; q < 4; ++q) {
        float bb = b_w[q * 256 + t];
#pragma unroll
        for (int w = 0; w < 8; ++w)
            g_wg[(s0 + w) * G4W + q * 256 + t] = acc[q][w] + bb;
    }
}

// ---------------- K2: sequential scan over an 8-CTA cluster ----------------
// CTA0 smem:
#define O_WC   0         // ull[16][512] char Whh k=96..127 (65536 B)
#define O_HC0  65536     // float[128] hc buffer 0
#define O_HC1  66048     // float[128] hc buffer 1
#define O_HW   66560     // float[256] hw
#define O_GW   67584     // float[1024] word gate dots (DSMEM target)
#define O_WOUT 71680     // float[17*256]
#define O_BOUT 89088     // float[17]
#define O_CH   89216     // int[17]
// worker smem:
#define O_WSS  0         // ull[3840]  smem-gate weights (30720 B)
#define O_XQ2  30720     // ull[4][52] per-quarter padded x pairs
#define O_XLIN 32384     // ull[192]   linear x pairs
#define SMEM_BYTES 92160

__global__ __launch_bounds__(512, 1) __cluster_dims__(NCTA, 1, 1)
void seq_kernel(const int*   __restrict__ word_chars,
                const int*   __restrict__ char_lens,
                const float* __restrict__ Whh_c,
                const float* __restrict__ Wout,
                const float* __restrict__ bout,
                float*       __restrict__ out) {

    extern __shared__ unsigned char smraw[];
    const int t = threadIdx.x;                 // 512
    const unsigned rank  = ctarank();
    const unsigned sbase = smem_u32(smraw);

    if (rank == 0) {
        // ================= char CTA + orchestrator =================
        ull*   sh_wc   = (ull*)(smraw + O_WC);
        float* sh_hc0  = (float*)(smraw + O_HC0);
        float* sh_hc1  = (float*)(smraw + O_HC1);
        float* sh_hw   = (float*)(smraw + O_HW);
        float* sh_gw   = (float*)(smraw + O_GW);
        float* sh_wout = (float*)(smraw + O_WOUT);
        float* sh_bout = (float*)(smraw + O_BOUT);
        int*   sh_ch   = (int*)(smraw + O_CH);

        const int q  = t & 3;            // gate type (i,f,g,o)
        const int il = t >> 2;           // hidden unit
        const int gg = q * HC_ + il;     // char gate index

        // char Whh row gg: k=0..95 in regs (48 pairs), k=96..127 in smem pair-major
        ull wr[48];
        {
            const ull* wrow = (const ull*)(Whh_c + gg * HC_);
#pragma unroll
            for (int i = 0; i < 48; ++i) wr[i] = wrow[i];
#pragma unroll
            for (int i = 0; i < 16; ++i) sh_wc[i * 512 + t] = wrow[48 + i];
        }
        for (int i = t; i < T_ * H_; i += 512) sh_wout[i] = Wout[i];
        if (t < T_) sh_bout[t] = bout[t];
        if (t < HC_) { sh_hc0[t] = 0.f; sh_hc1[t] = 0.f; }
        if (t < H_)  sh_hw[t] = 0.f;
        float ccr = 0.f;   // char cell (q==0 lanes, unit il)
        float cwr = 0.f;   // word cell (t<256)
        int cur = 0;       // which hc buffer holds live state
        const int lb = (t & 31) & ~3;    // lane base of this unit's 4-gate group
        __syncthreads();

        // -------- char phase for word 0 (direct staging) --------
        {
            if (t < LC_)  sh_ch[t]   = word_chars[t];
            if (t == LC_) sh_ch[LC_] = char_lens[0];
            __syncthreads();
            const int len = sh_ch[LC_];
            for (int ct = 0; ct < len; ++ct) {
                const int ch = sh_ch[ct];
                float xg = g_xg_tab[ch * G4C + gg];
                const ulonglong2* hq = (const ulonglong2*)(cur ? sh_hc1 : sh_hc0);
                float* dst = cur ? sh_hc0 : sh_hc1;
                ull a0 = 0, a1 = 0;
#pragma unroll
                for (int i = 0; i < 24; ++i) {
                    ulonglong2 hv = hq[i];
                    fma2(a0, wr[2 * i],     hv.x);
                    fma2(a1, wr[2 * i + 1], hv.y);
                }
#pragma unroll
                for (int i = 0; i < 8; ++i) {
                    ulonglong2 hv = hq[24 + i];
                    fma2(a0, sh_wc[(2 * i) * 512 + t],     hv.x);
                    fma2(a1, sh_wc[(2 * i + 1) * 512 + t], hv.y);
                }
                float v = xg + redu(a0) + redu(a1);
                float vf = __shfl_sync(0xffffffffu, v, lb | 1);
                float vg = __shfl_sync(0xffffffffu, v, lb | 2);
                float vo = __shfl_sync(0xffffffffu, v, lb | 3);
                if (q == 0) {
                    ccr = sigf(vf) * ccr + sigf(v) * tanh_(vg);
                    dst[il] = sigf(vo) * tanh_(ccr);
                }
                __syncthreads();
                cur ^= 1;
            }
        }

        for (int s = 0; s < S_; ++s) {
            // prefetch: word gate bias+we part for step s, chars for word s+1
            float wgl0 = 0.f, wgl1 = 0.f, wgl2 = 0.f, wgl3 = 0.f;
            if (t < H_) {
                wgl0 = g_wg[s * G4W + t];
                wgl1 = g_wg[s * G4W + 256 + t];
                wgl2 = g_wg[s * G4W + 512 + t];
                wgl3 = g_wg[s * G4W + 768 + t];
            }
            int chreg = 0;
            if (s + 1 < S_) {
                if (t < LC_)        chreg = word_chars[(s + 1) * LC_ + t];
                else if (t == LC_)  chreg = char_lens[s + 1];
            }

            // publish x(s) = [hc(s) | hw(s-1)] to L2
            if (t < 64)        stcg_u64(g_xbuf + t, ((const ull*)(cur ? sh_hc1 : sh_hc0))[t]);
            else if (t < 192)  stcg_u64(g_xbuf + t, ((const ull*)sh_hw)[t - 64]);
            cbar_arrive();                    // A_s: x visible to workers

            // logits(s-1) — off critical path, overlapped with workers
            if (s > 0) {
                int o = t >> 4; if (o > 16) o = 16;
                int l16 = t & 15;
                const float4* wo4 = (const float4*)sh_wout;
                const float4* xw4 = (const float4*)sh_hw;
                float acc = 0.f;
#pragma unroll
                for (int j = 0; j < 4; ++j) {
                    float4 w  = wo4[o * (H_/4) + l16 * 4 + j];
                    float4 xv = xw4[l16 * 4 + j];
                    acc += w.x * xv.x + w.y * xv.y + w.z * xv.z + w.w * xv.w;
                }
                acc += __shfl_xor_sync(0xffffffffu, acc, 8);
                acc += __shfl_xor_sync(0xffffffffu, acc, 4);
                acc += __shfl_xor_sync(0xffffffffu, acc, 2);
                acc += __shfl_xor_sync(0xffffffffu, acc, 1);
                if (t < T_ * 16 && l16 == 0) out[(s - 1) * T_ + o] = acc + sh_bout[o];
            }
            cbar_wait();                      // A_s complete

            // -------- char phase for word s+1 (overlaps worker gate compute) --------
            if (s + 1 < S_) {
                if (t < LC_ + 1) sh_ch[t] = chreg;
                __syncthreads();
                const int len = sh_ch[LC_];
                for (int ct = 0; ct < len; ++ct) {
                    const int ch = sh_ch[ct];
                    float xg = g_xg_tab[ch * G4C + gg];
                    const ulonglong2* hq = (const ulonglong2*)(cur ? sh_hc1 : sh_hc0);
                    float* dst = cur ? sh_hc0 : sh_hc1;
                    ull a0 = 0, a1 = 0;
#pragma unroll
                    for (int i = 0; i < 24; ++i) {
                        ulonglong2 hv = hq[i];
                        fma2(a0, wr[2 * i],     hv.x);
                        fma2(a1, wr[2 * i + 1], hv.y);
                    }
#pragma unroll
                    for (int i = 0; i < 8; ++i) {
                        ulonglong2 hv = hq[24 + i];
                        fma2(a0, sh_wc[(2 * i) * 512 + t],     hv.x);
                        fma2(a1, sh_wc[(2 * i + 1) * 512 + t], hv.y);
                    }
                    float v = xg + redu(a0) + redu(a1);
                    float vf = __shfl_sync(0xffffffffu, v, lb | 1);
                    float vg = __shfl_sync(0xffffffffu, v, lb | 2);
                    float vo = __shfl_sync(0xffffffffu, v, lb | 3);
                    if (q == 0) {
                        ccr = sigf(vf) * ccr + sigf(v) * tanh_(vg);
                        dst[il] = sigf(vo) * tanh_(ccr);
                    }
                    __syncthreads();
                    cur ^= 1;
                }
            }

            cbar_arrive();                    // B_s
            cbar_wait();                      // gates(s) landed in sh_gw

            // word activation for step s
            if (t < H_) {
                float gi = sigf(wgl0 + sh_gw[t]);
                float gf = sigf(wgl1 + sh_gw[256 + t]);
                float gga = tanh_(wgl2 + sh_gw[512 + t]);
                float go = sigf(wgl3 + sh_gw[768 + t]);
                cwr = gf * cwr + gi * gga;
                sh_hw[t] = go * tanh_(cwr);
            }
            __syncthreads();
        }

        // final logits for word S-1
        {
            int o = t >> 4; if (o > 16) o = 16;
            int l16 = t & 15;
            const float4* wo4 = (const float4*)sh_wout;
            const float4* xw4 = (const float4*)sh_hw;
            float acc = 0.f;
#pragma unroll
            for (int j = 0; j < 4; ++j) {
                float4 w  = wo4[o * (H_/4) + l16 * 4 + j];
                float4 xv = xw4[l16 * 4 + j];
                acc += w.x * xv.x + w.y * xv.y + w.z * xv.z + w.w * xv.w;
            }
            acc += __shfl_xor_sync(0xffffffffu, acc, 8);
            acc += __shfl_xor_sync(0xffffffffu, acc, 4);
            acc += __shfl_xor_sync(0xffffffffu, acc, 2);
            acc += __shfl_xor_sync(0xffffffffu, acc, 1);
            if (t < T_ * 16 && l16 == 0) out[(S_ - 1) * T_ + o] = acc + sh_bout[o];
        }
    } else {
        // ================= word-gate worker CTA =================
        ull* wss  = (ull*)(smraw + O_WSS);
        ull* xq2  = (ull*)(smraw + O_XQ2);
        ull* xlin = (ull*)(smraw + O_XLIN);
        const int r1  = (int)rank - 1;
        const int n_s = 18 + (r1 < 2 ? 1 : 0);
        const int gbase_s = 896 + r1 * 18 + (r1 < 2 ? r1 : 2);

        // register-resident weight slice: gate (r1*128 + t>>2), k quarter (t&3)
        ull wr[48];
#pragma unroll
        for (int j = 0; j < 48; ++j) wr[j] = g_Wreg[r1 * 24576 + j * 512 + t];
        for (int i = t; i < 3840; i += 512) wss[i] = g_Wss[r1 * 3840 + i];
        __syncthreads();

        const int il = t >> 2, q = t & 3;
        const int greg = r1 * 128 + il;                      // global gate of reg slice
        const unsigned gw_rem = mapa0(sbase + O_GW);         // CTA0 sh_gw
        const ulonglong2* xqp = (const ulonglong2*)(xq2 + q * 52);
        const int glc = (t >> 4) < n_s ? (t >> 4) : (n_s - 1);  // clamped smem-gate id
        const int l16 = t & 15;

        for (int s = 0; s < S_; ++s) {
            cbar_arrive();                 // A_s
            cbar_wait();                   // x(s) visible in L2
            if (t < 192) {                 // pull x, stage two layouts
                ull v = ldcg_u64(g_xbuf + t);
                int qq = t / 48, jj = t % 48;
                xq2[qq * 52 + jj] = v;
                xlin[t] = v;
            }
            __syncthreads();

            // reg gates: 96 k's per thread, 4 threads/gate
            ull a0 = 0, a1 = 0;
#pragma unroll
            for (int j2 = 0; j2 < 24; ++j2) {
                ulonglong2 xv = xqp[j2];
                fma2(a0, wr[2 * j2],     xv.x);
                fma2(a1, wr[2 * j2 + 1], xv.y);
            }
            float acc = redu(a0) + redu(a1);
            acc += __shfl_xor_sync(0xffffffffu, acc, 1);
            acc += __shfl_xor_sync(0xffffffffu, acc, 2);
            if (q == 0) st_dsm_f32(gw_rem + greg * 4, acc);

            // smem gates: 16 threads/gate, 24 k's each
            {
                ull a = 0;
#pragma unroll
                for (int jj = 0; jj < 12; ++jj) {
                    int p = jj * 16 + l16;
                    fma2(a, wss[p * 20 + glc], xlin[p]);
                }
                float a2 = redu(a);
                a2 += __shfl_xor_sync(0xffffffffu, a2, 1);
                a2 += __shfl_xor_sync(0xffffffffu, a2, 2);
                a2 += __shfl_xor_sync(0xffffffffu, a2, 4);
                a2 += __shfl_xor_sync(0xffffffffu, a2, 8);
                if (l16 == 0 && (t >> 4) < n_s)
                    st_dsm_f32(gw_rem + (gbase_s + glc) * 4, a2);
            }
            cbar_arrive();                 // B_s: gates delivered
            cbar_wait();
        }
    }
}

// ---------------- launch ----------------
extern "C" void kernel_launch(void* const* d_in, const int* in_sizes, int n_in,
                              void* d_out, int out_size) {
    const int*   sentence   = (const int*)  d_in[0];
    const int*   word_chars = (const int*)  d_in[1];
    const int*   char_lens  = (const int*)  d_in[2];
    const float* word_emb   = (const float*)d_in[3];
    const float* char_emb   = (const float*)d_in[4];
    const float* Wih_c      = (const float*)d_in[5];
    const float* Whh_c      = (const float*)d_in[6];
    const float* b_c        = (const float*)d_in[7];
    const float* Wih_w      = (const float*)d_in[8];
    const float* Whh_w      = (const float*)d_in[9];
    const float* b_w        = (const float*)d_in[10];
    const float* Wout       = (const float*)d_in[11];
    const float* bout       = (const float*)d_in[12];
    float* out = (float*)d_out;

    (void)in_sizes; (void)n_in; (void)out_size;

    prep_kernel<<<1024, 256>>>(Wih_w);
    slc_kernel<<<777, 256>>>(Wih_w, Whh_w);
    xg_kernel<<<CV_, G4C>>>(Wih_c, char_emb, b_c);
    wg_kernel<<<S_ / 8, 256>>>(sentence, word_emb, b_w);

    cudaFuncSetAttribute(seq_kernel,
                         cudaFuncAttributeMaxDynamicSharedMemorySize, SMEM_BYTES);
    seq_kernel<<<NCTA, 512, SMEM_BYTES>>>(word_chars, char_lens, Whh_c, Wout, bout, out);
}

// round 16
// speedup vs baseline: 2.9385x; 1.4048x over previous
#include <cuda_runtime.h>
#include <cuda_bf16.h>

// Problem constants
#define S_   8192
#define LC_  16
#define D_   256
#define CV_  128
#define DC_  64
#define HC_  128
#define H_   256
#define T_   17
// derived
#define G4C  (4*HC_)        // 512 char gates
#define G4W  (4*H_)         // 1024 word gates
#define KW   (HC_ + H_)     // 384 recurrent-x length for word LSTM
#define NCTA 8              // cluster: CTA0 = char/orchestrator, 1..7 = word workers

typedef unsigned long long ull;

// ---------------- device scratch (no allocation allowed) ----------------
__device__ __align__(16) float g_xg_tab[CV_ * G4C];        // 256 KB: per-char input gates
__device__ __align__(16) float g_wg[S_ * G4W];             // 32 MB : word-emb gate contributions (+b_w)
__device__ __align__(16) float g_WweT[(D_/4) * G4W * 4];   // 1 MB  : k-major we-part weights
__device__ __align__(16) ull   g_Wreg[7 * 512 * 48];       // 1.3 MB: per-thread register word-weight slices
__device__ __align__(16) ull   g_Wss [7 * 3840];           // 210 KB: per-worker smem-gate slices (pad 20)
__device__ __align__(16) ull   g_xbuf[192];                // 1.5 KB: x = [hc|hw] broadcast via L2

// ---------------- helpers ----------------
__device__ __forceinline__ void fma2(ull &acc, ull a, ull b) {
    asm("fma.rn.f32x2 %0, %1, %2, %0;" : "+l"(acc) : "l"(a), "l"(b));
}
__device__ __forceinline__ float redu(ull a) {
    return __uint_as_float((unsigned)(a & 0xffffffffull)) +
           __uint_as_float((unsigned)(a >> 32));
}
__device__ __forceinline__ float sigf(float x) {
    return __fdividef(1.0f, 1.0f + __expf(-x));
}
__device__ __forceinline__ float tanh_(float x) {
    float e = __expf(-2.0f * fabsf(x));
    float r = __fdividef(1.0f - e, 1.0f + e);
    return copysignf(r, x);
}
__device__ __forceinline__ unsigned smem_u32(const void* p) {
    unsigned a;
    asm("{ .reg .u64 t; cvta.to.shared.u64 t, %1; cvt.u32.u64 %0, t; }" : "=r"(a) : "l"(p));
    return a;
}
__device__ __forceinline__ unsigned ctarank() {
    unsigned r; asm("mov.u32 %0, %%cluster_ctarank;" : "=r"(r)); return r;
}
__device__ __forceinline__ unsigned mapa0(unsigned a) {
    unsigned r; asm("mapa.shared::cluster.u32 %0, %1, %2;" : "=r"(r) : "r"(a), "r"(0u)); return r;
}
__device__ __forceinline__ void st_dsm_f32(unsigned a, float v) {
    asm volatile("st.shared::cluster.f32 [%0], %1;" :: "r"(a), "f"(v));
}
__device__ __forceinline__ void cluster_sync_() {
    asm volatile("barrier.cluster.arrive.aligned;" ::: "memory");
    asm volatile("barrier.cluster.wait.aligned;" ::: "memory");
}
__device__ __forceinline__ void mbar_init(unsigned a, unsigned cnt) {
    asm volatile("mbarrier.init.shared.b64 [%0], %1;" :: "r"(a), "r"(cnt) : "memory");
}
// remote arrive on the same smem offset in cluster CTA `rank` (release.cluster)
__device__ __forceinline__ void mbar_arrive_remote(unsigned local_addr, unsigned rank) {
    asm volatile(
        "{\n\t.reg .b32 ra;\n\t"
        "mapa.shared::cluster.u32 ra, %0, %1;\n\t"
        "mbarrier.arrive.shared::cluster.b64 _, [ra];\n\t}"
        :: "r"(local_addr), "r"(rank) : "memory");
}
// local parity wait (spin on try_wait; acquire.cta is sufficient: payload is
// either local smem (DSMEM-pushed) or L2-routed .cg loads)
__device__ __forceinline__ void mbar_wait_par(unsigned a, unsigned par) {
    asm volatile(
        "{\n\t.reg .pred P;\n\t"
        "WL%=:\n\t"
        "mbarrier.try_wait.parity.shared::cta.b64 P, [%0], %1;\n\t"
        "@!P bra WL%=;\n\t}"
        :: "r"(a), "r"(par) : "memory");
}
__device__ __forceinline__ ull packf2(float lo, float hi) {
    return (ull)__float_as_uint(lo) | ((ull)__float_as_uint(hi) << 32);
}
__device__ __forceinline__ ull ldcg_u64(const ull* p) {
    ull v; asm volatile("ld.global.cg.b64 %0, [%1];" : "=l"(v) : "l"(p)); return v;
}
__device__ __forceinline__ void stcg_u64(ull* p, ull v) {
    asm volatile("st.global.cg.b64 [%0], %1;" :: "l"(p), "l"(v));
}

// ---------------- K0: per-char gate table ----------------
__global__ void xg_kernel(const float* __restrict__ Wih_c,
                          const float* __restrict__ char_emb,
                          const float* __restrict__ b_c) {
    __shared__ float ce[DC_];
    const int c = blockIdx.x, t = threadIdx.x;   // 128 blocks x 512 threads
    if (t < DC_) ce[t] = char_emb[c * DC_ + t];
    __syncthreads();
    float acc = b_c[t];
#pragma unroll
    for (int d = 0; d < DC_; ++d) acc += Wih_c[t * DC_ + d] * ce[d];
    g_xg_tab[c * G4C + t] = acc;
}

// ---------------- Kp: k-major we-part weights for the wg GEMM ----------------
__global__ void prep_kernel(const float* __restrict__ Wih_w) {
    int idx = blockIdx.x * blockDim.x + threadIdx.x;
    if (idx < (D_/4) * G4W * 4) {     // 262144
        int j  = idx & 3;
        int g  = (idx >> 2) & 1023;
        int k4 = idx >> 12;
        int k  = k4 * 4 + j;
        g_WweT[idx] = Wih_w[g * (D_ + HC_) + k];
    }
}

// ---------------- Ks: stage the recurrent word weights into cluster slices ----------------
__global__ void slc_kernel(const float* __restrict__ Wih_w,
                           const float* __restrict__ Whh_w) {
    const int NREG = 7 * 512 * 48;   // 172032
    const int NSS  = 7 * 3840;       // 26880
    int idx = blockIdx.x * blockDim.x + threadIdx.x;
    int g, k;
    ull* dst;
    if (idx < NREG) {
        int r1  = idx / (512 * 48);
        int rem = idx % (512 * 48);
        int j = rem / 512, t = rem % 512;
        int il = t >> 2, q = t & 3;
        g = r1 * 128 + il;            // 0..895
        k = q * 96 + 2 * j;
        dst = g_Wreg + idx;
    } else if (idx < NREG + NSS) {
        int e  = idx - NREG;
        int r1 = e / 3840;
        int o  = e % 3840;
        int p = o / 20, gl = o % 20;
        int n_s = 18 + (r1 < 2 ? 1 : 0);
        dst = g_Wss + e;
        if (gl >= n_s) { *dst = 0; return; }
        g = 896 + r1 * 18 + (r1 < 2 ? r1 : 2) + gl;   // 896..1023
        k = 2 * p;
    } else return;
    float v0 = (k     < HC_) ? Wih_w[g * (D_ + HC_) + D_ + k]     : Whh_w[g * H_ + (k     - HC_)];
    float v1 = (k + 1 < HC_) ? Wih_w[g * (D_ + HC_) + D_ + k + 1] : Whh_w[g * H_ + (k + 1 - HC_)];
    *dst = packf2(v0, v1);
}

// ---------------- K1: wg[s] = we_s @ Wih_w[:, :D].T + b_w (8 words/block) ----------------
__global__ __launch_bounds__(256) void wg_kernel(const int* __restrict__ sentence,
                                                 const float* __restrict__ word_emb,
                                                 const float* __restrict__ b_w) {
    __shared__ float sh_we[8 * D_];
    __shared__ int   sh_s[8];
    const int t = threadIdx.x;
    const int s0 = blockIdx.x * 8;
    if (t < 8) sh_s[t] = sentence[s0 + t];
    __syncthreads();
    for (int i = t; i < 8 * D_; i += 256) {
        int w = i >> 8, d = i & (D_ - 1);
        sh_we[i] = word_emb[(long long)sh_s[w] * D_ + d];
    }
    __syncthreads();

    float acc[4][8];
#pragma unroll
    for (int q = 0; q < 4; ++q)
#pragma unroll
        for (int w = 0; w < 8; ++w) acc[q][w] = 0.f;

    const float4* WT  = (const float4*)g_WweT;
    const float4* we4 = (const float4*)sh_we;
    for (int k4 = 0; k4 < D_/4; ++k4) {
        float4 wv[4];
#pragma unroll
        for (int q = 0; q < 4; ++q) wv[q] = WT[k4 * G4W + q * 256 + t];
#pragma unroll
        for (int w = 0; w < 8; ++w) {
            float4 xv = we4[w * (D_/4) + k4];
#pragma unroll
            for (int q = 0; q < 4; ++q)
                acc[q][w] += wv[q].x * xv.x + wv[q].y * xv.y +
                             wv[q].z * xv.z + wv[q].w * xv.w;
        }
    }
#pragma unroll
    for (int q = 0; q < 4; ++q) {
        float bb = b_w[q * 256 + t];
#pragma unroll
        for (int w = 0; w < 8; ++w)
            g_wg[(s0 + w) * G4W + q * 256 + t] = acc[q][w] + bb;
    }
}

// ---------------- K2: sequential scan over an 8-CTA cluster ----------------
// CTA0 smem:
#define O_WC    0         // ull[16][512] char Whh k=96..127 (65536 B)
#define O_HC0   65536     // float[128] hc buffer 0
#define O_HC1   66048     // float[128] hc buffer 1
#define O_HW    66560     // float[256] hw
#define O_GW    67584     // float[1024] word gate dots (DSMEM target)
#define O_WOUT  71680     // float[17*256]
#define O_BOUT  89088     // float[17]
#define O_CH    89216     // int[17]
#define O_GMB   89344     // mbarrier: gates done (count 7)
// worker smem:
#define O_WSS   0         // ull[3840]  smem-gate weights (30720 B)
#define O_XQ2   30720     // ull[4][52] per-quarter padded x pairs
#define O_XLIN  32384     // ull[192]   linear x pairs
#define O_XMB   33920     // mbarrier: x ready (count 1)
#define O_WOUTW 33984     // float[17*256] (rank 6 only)
#define O_BOUTW 51392     // float[17]     (rank 6 only)
#define SMEM_BYTES 92160

__global__ __launch_bounds__(512, 1) __cluster_dims__(NCTA, 1, 1)
void seq_kernel(const int*   __restrict__ word_chars,
                const int*   __restrict__ char_lens,
                const float* __restrict__ Whh_c,
                const float* __restrict__ Wout,
                const float* __restrict__ bout,
                float*       __restrict__ out) {

    extern __shared__ unsigned char smraw[];
    const int t = threadIdx.x;                 // 512
    const unsigned rank  = ctarank();
    const unsigned sbase = smem_u32(smraw);

    if (rank == 0) {
        // ================= char CTA + orchestrator =================
        ull*   sh_wc   = (ull*)(smraw + O_WC);
        float* sh_hc0  = (float*)(smraw + O_HC0);
        float* sh_hc1  = (float*)(smraw + O_HC1);
        float* sh_hw   = (float*)(smraw + O_HW);
        float* sh_gw   = (float*)(smraw + O_GW);
        float* sh_wout = (float*)(smraw + O_WOUT);
        float* sh_bout = (float*)(smraw + O_BOUT);
        int*   sh_ch   = (int*)(smraw + O_CH);

        const int q  = t & 3;            // gate type (i,f,g,o)
        const int il = t >> 2;           // hidden unit
        const int gg = q * HC_ + il;     // char gate index

        if (t == 0) mbar_init(sbase + O_GMB, 7);

        // char Whh row gg: k=0..95 in regs (48 pairs), k=96..127 in smem pair-major
        ull wr[48];
        {
            const ull* wrow = (const ull*)(Whh_c + gg * HC_);
#pragma unroll
            for (int i = 0; i < 48; ++i) wr[i] = wrow[i];
#pragma unroll
            for (int i = 0; i < 16; ++i) sh_wc[i * 512 + t] = wrow[48 + i];
        }
        for (int i = t; i < T_ * H_; i += 512) sh_wout[i] = Wout[i];
        if (t < T_) sh_bout[t] = bout[t];
        if (t < HC_) { sh_hc0[t] = 0.f; sh_hc1[t] = 0.f; }
        if (t < H_)  sh_hw[t] = 0.f;
        float ccr = 0.f;   // char cell (q==0 lanes, unit il)
        float cwr = 0.f;   // word cell (t<256)
        int cur = 0;       // which hc buffer holds live state
        const int lb = (t & 31) & ~3;    // lane base of this unit's 4-gate group
        __syncthreads();
        cluster_sync_();                 // mbarrier inits visible cluster-wide

        // -------- char phase for word 0 --------
        {
            if (t < LC_)  sh_ch[t]   = word_chars[t];
            if (t == LC_) sh_ch[LC_] = char_lens[0];
            __syncthreads();
            const int len = sh_ch[LC_];
            for (int ct = 0; ct < len; ++ct) {
                const int ch = sh_ch[ct];
                float xg = g_xg_tab[ch * G4C + gg];
                const ulonglong2* hq = (const ulonglong2*)(cur ? sh_hc1 : sh_hc0);
                float* dst = cur ? sh_hc0 : sh_hc1;
                ull a0 = 0, a1 = 0;
#pragma unroll
                for (int i = 0; i < 24; ++i) {
                    ulonglong2 hv = hq[i];
                    fma2(a0, wr[2 * i],     hv.x);
                    fma2(a1, wr[2 * i + 1], hv.y);
                }
#pragma unroll
                for (int i = 0; i < 8; ++i) {
                    ulonglong2 hv = hq[24 + i];
                    fma2(a0, sh_wc[(2 * i) * 512 + t],     hv.x);
                    fma2(a1, sh_wc[(2 * i + 1) * 512 + t], hv.y);
                }
                float v = xg + redu(a0) + redu(a1);
                float vf = __shfl_sync(0xffffffffu, v, lb | 1);
                float vg = __shfl_sync(0xffffffffu, v, lb | 2);
                float vo = __shfl_sync(0xffffffffu, v, lb | 3);
                if (q == 0) {
                    ccr = sigf(vf) * ccr + sigf(v) * tanh_(vg);
                    dst[il] = sigf(vo) * tanh_(ccr);
                }
                __syncthreads();
                cur ^= 1;
            }
        }

        for (int s = 0; s < S_; ++s) {
            // prefetch: word gate bias+we part for step s, chars for word s+1
            float wgl0 = 0.f, wgl1 = 0.f, wgl2 = 0.f, wgl3 = 0.f;
            if (t < H_) {
                wgl0 = g_wg[s * G4W + t];
                wgl1 = g_wg[s * G4W + 256 + t];
                wgl2 = g_wg[s * G4W + 512 + t];
                wgl3 = g_wg[s * G4W + 768 + t];
            }
            int chreg = 0;
            if (s + 1 < S_) {
                if (t < LC_)        chreg = word_chars[(s + 1) * LC_ + t];
                else if (t == LC_)  chreg = char_lens[s + 1];
            }

            // publish x(s) = [hc(s) | hw(s-1)] to L2; stage chars(s+1)
            if (t < 64)        stcg_u64(g_xbuf + t, ((const ull*)(cur ? sh_hc1 : sh_hc0))[t]);
            else if (t < 192)  stcg_u64(g_xbuf + t, ((const ull*)sh_hw)[t - 64]);
            if (t < LC_ + 1) sh_ch[t] = chreg;
            __syncthreads();                         // x stores + sh_ch visible CTA-wide
            if (t < 7) mbar_arrive_remote(sbase + O_XMB, t + 1);   // release: x ready

            // -------- char phase for word s+1 (overlaps worker gate compute) --------
            if (s + 1 < S_) {
                const int len = sh_ch[LC_];
                for (int ct = 0; ct < len; ++ct) {
                    const int ch = sh_ch[ct];
                    float xg = g_xg_tab[ch * G4C + gg];
                    const ulonglong2* hq = (const ulonglong2*)(cur ? sh_hc1 : sh_hc0);
                    float* dst = cur ? sh_hc0 : sh_hc1;
                    ull a0 = 0, a1 = 0;
#pragma unroll
                    for (int i = 0; i < 24; ++i) {
                        ulonglong2 hv = hq[i];
                        fma2(a0, wr[2 * i],     hv.x);
                        fma2(a1, wr[2 * i + 1], hv.y);
                    }
#pragma unroll
                    for (int i = 0; i < 8; ++i) {
                        ulonglong2 hv = hq[24 + i];
                        fma2(a0, sh_wc[(2 * i) * 512 + t],     hv.x);
                        fma2(a1, sh_wc[(2 * i + 1) * 512 + t], hv.y);
                    }
                    float v = xg + redu(a0) + redu(a1);
                    float vf = __shfl_sync(0xffffffffu, v, lb | 1);
                    float vg = __shfl_sync(0xffffffffu, v, lb | 2);
                    float vo = __shfl_sync(0xffffffffu, v, lb | 3);
                    if (q == 0) {
                        ccr = sigf(vf) * ccr + sigf(v) * tanh_(vg);
                        dst[il] = sigf(vo) * tanh_(ccr);
                    }
                    __syncthreads();
                    cur ^= 1;
                }
            }

            mbar_wait_par(sbase + O_GMB, s & 1);     // gates(s) landed in sh_gw

            // word activation for step s
            if (t < H_) {
                float gi  = sigf(wgl0 + sh_gw[t]);
                float gf  = sigf(wgl1 + sh_gw[256 + t]);
                float gga = tanh_(wgl2 + sh_gw[512 + t]);
                float go  = sigf(wgl3 + sh_gw[768 + t]);
                cwr = gf * cwr + gi * gga;
                sh_hw[t] = go * tanh_(cwr);
            }
            __syncthreads();
        }

        // final logits for word S-1 (workers never see hw(S-1))
        {
            int o = t >> 4; if (o > 16) o = 16;
            int l16 = t & 15;
            const float4* wo4 = (const float4*)sh_wout;
            const float4* xw4 = (const float4*)sh_hw;
            float acc = 0.f;
#pragma unroll
            for (int j = 0; j < 4; ++j) {
                float4 w  = wo4[o * (H_/4) + l16 * 4 + j];
                float4 xv = xw4[l16 * 4 + j];
                acc += w.x * xv.x + w.y * xv.y + w.z * xv.z + w.w * xv.w;
            }
            acc += __shfl_xor_sync(0xffffffffu, acc, 8);
            acc += __shfl_xor_sync(0xffffffffu, acc, 4);
            acc += __shfl_xor_sync(0xffffffffu, acc, 2);
            acc += __shfl_xor_sync(0xffffffffu, acc, 1);
            if (t < T_ * 16 && l16 == 0) out[(S_ - 1) * T_ + o] = acc + sh_bout[o];
        }
        cluster_sync_();                 // drain before exit
    } else {
        // ================= word-gate worker CTA =================
        ull*   wss   = (ull*)(smraw + O_WSS);
        ull*   xq2   = (ull*)(smraw + O_XQ2);
        ull*   xlin  = (ull*)(smraw + O_XLIN);
        float* woutw = (float*)(smraw + O_WOUTW);
        float* boutw = (float*)(smraw + O_BOUTW);
        const int r1  = (int)rank - 1;
        const int n_s = 18 + (r1 < 2 ? 1 : 0);
        const int gbase_s = 896 + r1 * 18 + (r1 < 2 ? r1 : 2);
        const bool do_logits = (r1 == 5);

        if (t == 0) mbar_init(sbase + O_XMB, 1);

        // register-resident weight slice: gate (r1*128 + t>>2), k quarter (t&3)
        ull wr[48];
#pragma unroll
        for (int j = 0; j < 48; ++j) wr[j] = g_Wreg[r1 * 24576 + j * 512 + t];
        for (int i = t; i < 3840; i += 512) wss[i] = g_Wss[r1 * 3840 + i];
        if (do_logits) {
            for (int i = t; i < T_ * H_; i += 512) woutw[i] = Wout[i];
            if (t < T_) boutw[t] = bout[t];
        }
        __syncthreads();
        cluster_sync_();                 // mbarrier inits visible cluster-wide

        const int il = t >> 2, q = t & 3;
        const int greg = r1 * 128 + il;                      // global gate of reg slice
        const unsigned gw_rem = mapa0(sbase + O_GW);         // CTA0 sh_gw
        const ulonglong2* xqp = (const ulonglong2*)(xq2 + q * 52);
        const int glc = (t >> 4) < n_s ? (t >> 4) : (n_s - 1);  // clamped smem-gate id
        const int l16 = t & 15;

        for (int s = 0; s < S_; ++s) {
            mbar_wait_par(sbase + O_XMB, s & 1);   // x(s) ready (L2)
            if (t < 192) {                         // pull x, stage two layouts
                ull v = ldcg_u64(g_xbuf + t);
                int qq = t / 48, jj = t % 48;
                xq2[qq * 52 + jj] = v;
                xlin[t] = v;
            }
            __syncthreads();

            // reg gates: 96 k's per thread, 4 threads/gate
            ull a0 = 0, a1 = 0;
#pragma unroll
            for (int j2 = 0; j2 < 24; ++j2) {
                ulonglong2 xv = xqp[j2];
                fma2(a0, wr[2 * j2],     xv.x);
                fma2(a1, wr[2 * j2 + 1], xv.y);
            }
            float acc = redu(a0) + redu(a1);
            acc += __shfl_xor_sync(0xffffffffu, acc, 1);
            acc += __shfl_xor_sync(0xffffffffu, acc, 2);
            if (q == 0) st_dsm_f32(gw_rem + greg * 4, acc);

            // smem gates: 16 threads/gate, 24 k's each
            {
                ull a = 0;
#pragma unroll
                for (int jj = 0; jj < 12; ++jj) {
                    int p = jj * 16 + l16;
                    fma2(a, wss[p * 20 + glc], xlin[p]);
                }
                float a2 = redu(a);
                a2 += __shfl_xor_sync(0xffffffffu, a2, 1);
                a2 += __shfl_xor_sync(0xffffffffu, a2, 2);
                a2 += __shfl_xor_sync(0xffffffffu, a2, 4);
                a2 += __shfl_xor_sync(0xffffffffu, a2, 8);
                if (l16 == 0 && (t >> 4) < n_s)
                    st_dsm_f32(gw_rem + (gbase_s + glc) * 4, a2);
            }
            __syncthreads();                       // all gate pushes issued
            if (t == 0) mbar_arrive_remote(sbase + O_GMB, 0);   // release -> CTA0

            // logits(s-1) from hw inside x(s) — fully off the critical path
            if (do_logits && s > 0) {
                int o = t >> 4; if (o > 16) o = 16;
                const float2* w2 = (const float2*)woutw + o * 128 + l16 * 8;
                const float2* x2 = (const float2*)(xlin + 64) + l16 * 8;
                float la = 0.f;
#pragma unroll
                for (int j = 0; j < 8; ++j)
                    la += w2[j].x * x2[j].x + w2[j].y * x2[j].y;
                la += __shfl_xor_sync(0xffffffffu, la, 8);
                la += __shfl_xor_sync(0xffffffffu, la, 4);
                la += __shfl_xor_sync(0xffffffffu, la, 2);
                la += __shfl_xor_sync(0xffffffffu, la, 1);
                if (t < T_ * 16 && l16 == 0) out[(s - 1) * T_ + o] = la + boutw[o];
            }
        }
        cluster_sync_();                 // drain before exit
    }
}

// ---------------- launch ----------------
extern "C" void kernel_launch(void* const* d_in, const int* in_sizes, int n_in,
                              void* d_out, int out_size) {
    const int*   sentence   = (const int*)  d_in[0];
    const int*   word_chars = (const int*)  d_in[1];
    const int*   char_lens  = (const int*)  d_in[2];
    const float* word_emb   = (const float*)d_in[3];
    const float* char_emb   = (const float*)d_in[4];
    const float* Wih_c      = (const float*)d_in[5];
    const float* Whh_c      = (const float*)d_in[6];
    const float* b_c        = (const float*)d_in[7];
    const float* Wih_w      = (const float*)d_in[8];
    const float* Whh_w      = (const float*)d_in[9];
    const float* b_w        = (const float*)d_in[10];
    const float* Wout       = (const float*)d_in[11];
    const float* bout       = (const float*)d_in[12];
    float* out = (float*)d_out;

    (void)in_sizes; (void)n_in; (void)out_size;

    prep_kernel<<<1024, 256>>>(Wih_w);
    slc_kernel<<<777, 256>>>(Wih_w, Whh_w);
    xg_kernel<<<CV_, G4C>>>(Wih_c, char_emb, b_c);
    wg_kernel<<<S_ / 8, 256>>>(sentence, word_emb, b_w);

    cudaFuncSetAttribute(seq_kernel,
                         cudaFuncAttributeMaxDynamicSharedMemorySize, SMEM_BYTES);
    seq_kernel<<<NCTA, 512, SMEM_BYTES>>>(word_chars, char_lens, Whh_c, Wout, bout, out);
}